// round 1
// baseline (speedup 1.0000x reference)
#include <cuda_runtime.h>

#define B_SZ  4
#define S_LEN 2048
#define C_DIM 1024
#define H_NUM 16
#define D_DIM 64
#define BHN   (B_SZ * H_NUM)

// Scratch: Q,K,V in [B,H,S,D] layout; attention output back in [B,S,C] layout.
__device__ float g_q[BHN * S_LEN * D_DIM];
__device__ float g_k[BHN * S_LEN * D_DIM];
__device__ float g_v[BHN * S_LEN * D_DIM];
__device__ float g_ao[B_SZ * S_LEN * C_DIM];

// ---------------------------------------------------------------------------
// SGEMM: C[M,N] = A[M,K] @ B[K,N] + bias[N]
// MODE 0: A = x, epilogue scatters into g_q/g_k/g_v ([B,H,S,D])
// MODE 1: A = g_ao, epilogue writes Cout row-major
// BM=BN=128, BK=8, 256 threads, 8x8 microtile.
// ---------------------------------------------------------------------------
template <int MODE>
__global__ void __launch_bounds__(256, 2) sgemm_k(
    const float* __restrict__ A, const float* __restrict__ Bm,
    const float* __restrict__ bias, float* __restrict__ Cout,
    int M, int N, int K)
{
    constexpr int BM = 128, BN = 128, BK = 8;
    __shared__ float As[BK][BM];
    __shared__ float Bs[BK][BN];

    const float* Ap = (MODE == 1) ? (const float*)g_ao : A;

    int tid = threadIdx.x;
    int rowBlk = blockIdx.y * BM;
    int colBlk = blockIdx.x * BN;
    int tr = tid >> 4;        // 0..15
    int tc = tid & 15;        // 0..15

    int aRow = tid >> 1;          // 0..127
    int aK4  = (tid & 1) * 4;     // 0 or 4
    int bRow = tid >> 5;          // 0..7
    int bC4  = (tid & 31) * 4;    // 0..124

    const float* aPtr = Ap + (size_t)(rowBlk + aRow) * K + aK4;
    const float* bPtr = Bm + (size_t)bRow * N + colBlk + bC4;

    float acc[8][8];
    #pragma unroll
    for (int i = 0; i < 8; i++)
        #pragma unroll
        for (int j = 0; j < 8; j++) acc[i][j] = 0.f;

    for (int kt = 0; kt < K; kt += BK) {
        float4 av = *(const float4*)(aPtr + kt);
        float4 bv = *(const float4*)(bPtr + (size_t)kt * N);
        As[aK4 + 0][aRow] = av.x;
        As[aK4 + 1][aRow] = av.y;
        As[aK4 + 2][aRow] = av.z;
        As[aK4 + 3][aRow] = av.w;
        *(float4*)&Bs[bRow][bC4] = bv;
        __syncthreads();

        #pragma unroll
        for (int k = 0; k < BK; k++) {
            float ar[8], br[8];
            *(float4*)(ar)     = *(const float4*)&As[k][tr * 8];
            *(float4*)(ar + 4) = *(const float4*)&As[k][tr * 8 + 4];
            *(float4*)(br)     = *(const float4*)&Bs[k][tc * 8];
            *(float4*)(br + 4) = *(const float4*)&Bs[k][tc * 8 + 4];
            #pragma unroll
            for (int i = 0; i < 8; i++)
                #pragma unroll
                for (int j = 0; j < 8; j++)
                    acc[i][j] += ar[i] * br[j];
        }
        __syncthreads();
    }

    int col0 = colBlk + tc * 8;
    float bb[8];
    *(float4*)(bb)     = *(const float4*)(bias + col0);
    *(float4*)(bb + 4) = *(const float4*)(bias + col0 + 4);

    if (MODE == 0) {
        // col0..col0+7 all lie inside one of q/k/v and one head (8 | 64 | 1024)
        int which = col0 / C_DIM;
        int cc    = col0 % C_DIM;
        int h  = cc / D_DIM;
        int d0 = cc % D_DIM;
        float* dst = (which == 0) ? g_q : (which == 1) ? g_k : g_v;
        #pragma unroll
        for (int i = 0; i < 8; i++) {
            int m = rowBlk + tr * 8 + i;
            int b = m >> 11;          // / S_LEN
            int s = m & (S_LEN - 1);
            float* p = dst + ((size_t)(b * H_NUM + h) * S_LEN + s) * D_DIM + d0;
            float4 v0 = make_float4(acc[i][0] + bb[0], acc[i][1] + bb[1],
                                    acc[i][2] + bb[2], acc[i][3] + bb[3]);
            float4 v1 = make_float4(acc[i][4] + bb[4], acc[i][5] + bb[5],
                                    acc[i][6] + bb[6], acc[i][7] + bb[7]);
            *(float4*)p       = v0;
            *(float4*)(p + 4) = v1;
        }
    } else {
        #pragma unroll
        for (int i = 0; i < 8; i++) {
            int m = rowBlk + tr * 8 + i;
            float* p = Cout + (size_t)m * N + col0;
            float4 v0 = make_float4(acc[i][0] + bb[0], acc[i][1] + bb[1],
                                    acc[i][2] + bb[2], acc[i][3] + bb[3]);
            float4 v1 = make_float4(acc[i][4] + bb[4], acc[i][5] + bb[5],
                                    acc[i][6] + bb[6], acc[i][7] + bb[7]);
            *(float4*)p       = v0;
            *(float4*)(p + 4) = v1;
        }
    }
}

// ---------------------------------------------------------------------------
// Causal flash attention, fp32. One block = one (b,h) x 64-row Q tile.
// 256 threads: thread (r, c4) = (tid>>2, tid&3) owns Q row r and d-range
// [c4*16, c4*16+16). K tiles of 64 rows; online softmax. After scores are
// computed (registers), K smem is overlaid with the P (softmax) tile.
// ---------------------------------------------------------------------------
__global__ void __launch_bounds__(256) attn_k()
{
    __shared__ float kp_sm[64][65];   // K tile, then reused for P (and Q staging)
    __shared__ float v_sm[64][65];    // V tile

    int tid = threadIdx.x;
    int r  = tid >> 2;
    int c4 = tid & 3;
    int qt = blockIdx.x;
    int bh = blockIdx.y;

    const float* qb = g_q + (size_t)bh * S_LEN * D_DIM;
    const float* kb = g_k + (size_t)bh * S_LEN * D_DIM;
    const float* vb = g_v + (size_t)bh * S_LEN * D_DIM;

    // Stage Q tile through smem, then each thread keeps its row in registers
    for (int i = tid; i < 64 * 16; i += 256) {
        int rr = i >> 4, dd = (i & 15) * 4;
        float4 qv = *(const float4*)(qb + (size_t)(qt * 64 + rr) * D_DIM + dd);
        kp_sm[rr][dd]     = qv.x;
        kp_sm[rr][dd + 1] = qv.y;
        kp_sm[rr][dd + 2] = qv.z;
        kp_sm[rr][dd + 3] = qv.w;
    }
    __syncthreads();
    float q_reg[64];
    #pragma unroll
    for (int d = 0; d < 64; d++) q_reg[d] = kp_sm[r][d] * 0.125f;  // 1/sqrt(64)

    float m_i = -1e30f, l_i = 0.f;
    float acc[16];
    #pragma unroll
    for (int j = 0; j < 16; j++) acc[j] = 0.f;

    int qrow = qt * 64 + r;
    int d0 = c4 * 16;

    for (int kt = 0; kt <= qt; kt++) {
        __syncthreads();  // previous iteration fully consumed kp_sm / v_sm
        for (int i = tid; i < 64 * 16; i += 256) {
            int rr = i >> 4, dd = (i & 15) * 4;
            size_t base = (size_t)(kt * 64 + rr) * D_DIM + dd;
            float4 kv = *(const float4*)(kb + base);
            kp_sm[rr][dd]     = kv.x;
            kp_sm[rr][dd + 1] = kv.y;
            kp_sm[rr][dd + 2] = kv.z;
            kp_sm[rr][dd + 3] = kv.w;
            float4 vv = *(const float4*)(vb + base);
            v_sm[rr][dd]     = vv.x;
            v_sm[rr][dd + 1] = vv.y;
            v_sm[rr][dd + 2] = vv.z;
            v_sm[rr][dd + 3] = vv.w;
        }
        __syncthreads();

        // Scores for this thread's 16 K columns (Q pre-scaled)
        float sreg[16];
        #pragma unroll
        for (int i = 0; i < 16; i++) {
            int kk = d0 + i;
            float s = 0.f;
            #pragma unroll
            for (int d = 0; d < 64; d++) s += q_reg[d] * kp_sm[kk][d];
            sreg[i] = ((kt * 64 + kk) <= qrow) ? s : -1e30f;
        }
        __syncthreads();  // everyone done reading K before overlay with P

        // Row max across this thread's 16, then across the 4 lanes of the row
        float mt = sreg[0];
        #pragma unroll
        for (int i = 1; i < 16; i++) mt = fmaxf(mt, sreg[i]);
        mt = fmaxf(mt, __shfl_xor_sync(0xffffffffu, mt, 1));
        mt = fmaxf(mt, __shfl_xor_sync(0xffffffffu, mt, 2));
        float m_new   = fmaxf(m_i, mt);
        float rescale = __expf(m_i - m_new);

        float psum = 0.f;
        #pragma unroll
        for (int i = 0; i < 16; i++) {
            float p = __expf(sreg[i] - m_new);
            psum += p;
            kp_sm[r][d0 + i] = p;   // overlay: kp_sm now holds P[qrow][k]
        }
        psum += __shfl_xor_sync(0xffffffffu, psum, 1);
        psum += __shfl_xor_sync(0xffffffffu, psum, 2);
        l_i = l_i * rescale + psum;
        m_i = m_new;
        #pragma unroll
        for (int j = 0; j < 16; j++) acc[j] *= rescale;
        __syncwarp();   // P for row r written by this warp's own 4 lanes

        // acc += P @ V
        #pragma unroll 4
        for (int k = 0; k < 64; k++) {
            float p = kp_sm[r][k];
            #pragma unroll
            for (int j = 0; j < 16; j++)
                acc[j] += p * v_sm[k][d0 + j];
        }
    }

    float inv = 1.f / l_i;
    int b = bh >> 4, h = bh & 15;
    float* op = g_ao + (size_t)(b * S_LEN + qrow) * C_DIM + h * D_DIM + d0;
    #pragma unroll
    for (int j = 0; j < 16; j += 4) {
        float4 o = make_float4(acc[j] * inv, acc[j + 1] * inv,
                               acc[j + 2] * inv, acc[j + 3] * inv);
        *(float4*)(op + j) = o;
    }
}

// ---------------------------------------------------------------------------
extern "C" void kernel_launch(void* const* d_in, const int* in_sizes, int n_in,
                              void* d_out, int out_size)
{
    const float* x      = (const float*)d_in[0];
    const float* w_qkv  = (const float*)d_in[1];
    const float* b_qkv  = (const float*)d_in[2];
    const float* w_proj = (const float*)d_in[3];
    const float* b_proj = (const float*)d_in[4];
    float* out = (float*)d_out;

    const int M = B_SZ * S_LEN;  // 8192

    // 1) QKV GEMM + bias, scattered into [B,H,S,D] q/k/v
    sgemm_k<0><<<dim3((3 * C_DIM) / 128, M / 128), 256>>>(
        x, w_qkv, b_qkv, nullptr, M, 3 * C_DIM, C_DIM);

    // 2) Causal flash attention -> g_ao in [B,S,C]
    attn_k<<<dim3(S_LEN / 64, BHN), 256>>>();

    // 3) Output projection + bias
    sgemm_k<1><<<dim3(C_DIM / 128, M / 128), 256>>>(
        nullptr, w_proj, b_proj, out, M, C_DIM, C_DIM);
}

// round 2
// speedup vs baseline: 1.2212x; 1.2212x over previous
#include <cuda_runtime.h>
#include <cstdint>

#define B_SZ  4
#define S_LEN 2048
#define C_DIM 1024
#define H_NUM 16
#define D_DIM 64
#define BHN   (B_SZ * H_NUM)

// Scratch: Q,K,V in [B,H,S,D] layout; attention output back in [B,S,C] layout.
__device__ float g_q[BHN * S_LEN * D_DIM];
__device__ float g_k[BHN * S_LEN * D_DIM];
__device__ float g_v[BHN * S_LEN * D_DIM];
__device__ float g_ao[B_SZ * S_LEN * C_DIM];

// ---------------------------------------------------------------------------
// Helpers: cp.async + tf32 mma
// ---------------------------------------------------------------------------
__device__ __forceinline__ void cp_async16(void* smem_dst, const void* gmem_src) {
    uint32_t s = (uint32_t)__cvta_generic_to_shared(smem_dst);
    asm volatile("cp.async.cg.shared.global [%0], [%1], 16;\n" :: "r"(s), "l"(gmem_src));
}
__device__ __forceinline__ void cp_commit() {
    asm volatile("cp.async.commit_group;\n");
}
template <int N>
__device__ __forceinline__ void cp_wait() {
    asm volatile("cp.async.wait_group %0;\n" :: "n"(N));
}
__device__ __forceinline__ uint32_t f2tf32(float f) {
    uint32_t r;
    asm("cvt.rna.tf32.f32 %0, %1;\n" : "=r"(r) : "f"(f));
    return r;
}
__device__ __forceinline__ void mma_tf32(float c[4], const uint32_t a[4], const uint32_t b[2]) {
    asm volatile(
        "mma.sync.aligned.m16n8k8.row.col.f32.tf32.tf32.f32 "
        "{%0,%1,%2,%3}, {%4,%5,%6,%7}, {%8,%9}, {%0,%1,%2,%3};\n"
        : "+f"(c[0]), "+f"(c[1]), "+f"(c[2]), "+f"(c[3])
        : "r"(a[0]), "r"(a[1]), "r"(a[2]), "r"(a[3]), "r"(b[0]), "r"(b[1]));
}

// ---------------------------------------------------------------------------
// TF32 tensor-core GEMM: C[M,N] = A[M,K] @ B[K,N] + bias[N]
// MODE 0: A = x, epilogue scatters into g_q/g_k/g_v ([B,H,S,D])
// MODE 1: A = g_ao, epilogue writes Cout row-major
// BM=BN=128, BK=16, 256 threads (8 warps, 4x2), warp tile 32x64,
// cp.async double-buffered smem.
// ---------------------------------------------------------------------------
#define A_STRIDE 20    // 16 + 4 pad (floats) — conflict-free A fragment LDS
#define B_STRIDE 136   // 128 + 8 pad (floats) — conflict-free B fragment LDS

template <int MODE>
__global__ void __launch_bounds__(256, 2) sgemm_tf32_k(
    const float* __restrict__ A, const float* __restrict__ Bm,
    const float* __restrict__ bias, float* __restrict__ Cout,
    int M, int N, int K)
{
    constexpr int BM = 128, BN = 128, BK = 16;
    __shared__ float As[2][BM * A_STRIDE];   // [m][k] row-major, padded
    __shared__ float Bs[2][BK * B_STRIDE];   // [k][n] row-major, padded

    const float* Ap = (MODE == 1) ? (const float*)g_ao : A;

    const int tid  = threadIdx.x;
    const int lane = tid & 31;
    const int wid  = tid >> 5;
    const int wm   = wid & 3;   // 0..3 -> m offset wm*32
    const int wn   = wid >> 2;  // 0..1 -> n offset wn*64
    const int lr   = lane >> 2; // 0..7
    const int lc   = lane & 3;  // 0..3

    const int rowBlk = blockIdx.y * BM;
    const int colBlk = blockIdx.x * BN;

    // cp.async chunk mapping (4 x 16B per thread per tile)
    // A tile: 128 rows x 16 floats = 512 chunks; chunk c: row=c/4, k=(c%4)*4
    // B tile: 16 rows x 128 floats = 512 chunks; chunk c: row=c/32, n=(c%32)*4
    const int aRow0 = tid >> 1;                  // 2 chunks per row pair mapping:
    // use c = tid*2 + {0,1}
    const int NK = K / BK;

    auto issue_stage = [&](int buf, int kt) {
        #pragma unroll
        for (int u = 0; u < 2; u++) {
            int c = tid * 2 + u;
            int ar = c >> 2;            // 0..127
            int ak = (c & 3) * 4;       // 0,4,8,12
            cp_async16(&As[buf][ar * A_STRIDE + ak],
                       Ap + (size_t)(rowBlk + ar) * K + kt * BK + ak);
            int br = c >> 5;            // 0..15
            int bn = (c & 31) * 4;      // 0..124
            cp_async16(&Bs[buf][br * B_STRIDE + bn],
                       Bm + (size_t)(kt * BK + br) * N + colBlk + bn);
        }
        cp_commit();
    };
    (void)aRow0;

    float acc[2][8][4];
    #pragma unroll
    for (int mt = 0; mt < 2; mt++)
        #pragma unroll
        for (int nt = 0; nt < 8; nt++)
            #pragma unroll
            for (int i = 0; i < 4; i++) acc[mt][nt][i] = 0.f;

    issue_stage(0, 0);

    for (int kt = 0; kt < NK; kt++) {
        if (kt + 1 < NK) {
            issue_stage((kt + 1) & 1, kt + 1);
            cp_wait<1>();
        } else {
            cp_wait<0>();
        }
        __syncthreads();

        const float* As_ = As[kt & 1];
        const float* Bs_ = Bs[kt & 1];

        #pragma unroll
        for (int ks = 0; ks < 2; ks++) {
            const int kk = ks * 8;
            uint32_t afr[2][4];
            #pragma unroll
            for (int mt = 0; mt < 2; mt++) {
                int m0 = wm * 32 + mt * 16 + lr;
                afr[mt][0] = f2tf32(As_[m0 * A_STRIDE + kk + lc]);
                afr[mt][1] = f2tf32(As_[(m0 + 8) * A_STRIDE + kk + lc]);
                afr[mt][2] = f2tf32(As_[m0 * A_STRIDE + kk + lc + 4]);
                afr[mt][3] = f2tf32(As_[(m0 + 8) * A_STRIDE + kk + lc + 4]);
            }
            uint32_t bfr[8][2];
            #pragma unroll
            for (int nt = 0; nt < 8; nt++) {
                int n0 = wn * 64 + nt * 8 + lr;
                bfr[nt][0] = f2tf32(Bs_[(kk + lc) * B_STRIDE + n0]);
                bfr[nt][1] = f2tf32(Bs_[(kk + lc + 4) * B_STRIDE + n0]);
            }
            #pragma unroll
            for (int mt = 0; mt < 2; mt++)
                #pragma unroll
                for (int nt = 0; nt < 8; nt++)
                    mma_tf32(acc[mt][nt], afr[mt], bfr[nt]);
        }
        __syncthreads();
    }

    // Epilogue: acc[mt][nt] tile (m16 x n8), this lane owns
    //   rows lr, lr+8; cols lc*2, lc*2+1
    #pragma unroll
    for (int nt = 0; nt < 8; nt++) {
        int col = colBlk + wn * 64 + nt * 8 + lc * 2;
        float2 bb = *(const float2*)(bias + col);
        if (MODE == 0) {
            int which = col / C_DIM;
            int cc    = col % C_DIM;
            int h  = cc / D_DIM;
            int d0 = cc % D_DIM;
            float* dst = (which == 0) ? g_q : (which == 1) ? g_k : g_v;
            #pragma unroll
            for (int mt = 0; mt < 2; mt++) {
                int r0 = rowBlk + wm * 32 + mt * 16 + lr;
                #pragma unroll
                for (int half = 0; half < 2; half++) {
                    int m = r0 + half * 8;
                    int b = m >> 11;
                    int s = m & (S_LEN - 1);
                    float* p = dst + ((size_t)(b * H_NUM + h) * S_LEN + s) * D_DIM + d0;
                    float2 v = make_float2(acc[mt][nt][half * 2 + 0] + bb.x,
                                           acc[mt][nt][half * 2 + 1] + bb.y);
                    *(float2*)p = v;
                }
            }
        } else {
            #pragma unroll
            for (int mt = 0; mt < 2; mt++) {
                int r0 = rowBlk + wm * 32 + mt * 16 + lr;
                #pragma unroll
                for (int half = 0; half < 2; half++) {
                    int m = r0 + half * 8;
                    float* p = Cout + (size_t)m * N + col;
                    float2 v = make_float2(acc[mt][nt][half * 2 + 0] + bb.x,
                                           acc[mt][nt][half * 2 + 1] + bb.y);
                    *(float2*)p = v;
                }
            }
        }
    }
}

// ---------------------------------------------------------------------------
// Causal flash attention, fp32 (unchanged from R1 — known good).
// ---------------------------------------------------------------------------
__global__ void __launch_bounds__(256) attn_k()
{
    __shared__ float kp_sm[64][65];   // K tile, then reused for P (and Q staging)
    __shared__ float v_sm[64][65];    // V tile

    int tid = threadIdx.x;
    int r  = tid >> 2;
    int c4 = tid & 3;
    int qt = blockIdx.x;
    int bh = blockIdx.y;

    const float* qb = g_q + (size_t)bh * S_LEN * D_DIM;
    const float* kb = g_k + (size_t)bh * S_LEN * D_DIM;
    const float* vb = g_v + (size_t)bh * S_LEN * D_DIM;

    for (int i = tid; i < 64 * 16; i += 256) {
        int rr = i >> 4, dd = (i & 15) * 4;
        float4 qv = *(const float4*)(qb + (size_t)(qt * 64 + rr) * D_DIM + dd);
        kp_sm[rr][dd]     = qv.x;
        kp_sm[rr][dd + 1] = qv.y;
        kp_sm[rr][dd + 2] = qv.z;
        kp_sm[rr][dd + 3] = qv.w;
    }
    __syncthreads();
    float q_reg[64];
    #pragma unroll
    for (int d = 0; d < 64; d++) q_reg[d] = kp_sm[r][d] * 0.125f;  // 1/sqrt(64)

    float m_i = -1e30f, l_i = 0.f;
    float acc[16];
    #pragma unroll
    for (int j = 0; j < 16; j++) acc[j] = 0.f;

    int qrow = qt * 64 + r;
    int d0 = c4 * 16;

    for (int kt = 0; kt <= qt; kt++) {
        __syncthreads();
        for (int i = tid; i < 64 * 16; i += 256) {
            int rr = i >> 4, dd = (i & 15) * 4;
            size_t base = (size_t)(kt * 64 + rr) * D_DIM + dd;
            float4 kv = *(const float4*)(kb + base);
            kp_sm[rr][dd]     = kv.x;
            kp_sm[rr][dd + 1] = kv.y;
            kp_sm[rr][dd + 2] = kv.z;
            kp_sm[rr][dd + 3] = kv.w;
            float4 vv = *(const float4*)(vb + base);
            v_sm[rr][dd]     = vv.x;
            v_sm[rr][dd + 1] = vv.y;
            v_sm[rr][dd + 2] = vv.z;
            v_sm[rr][dd + 3] = vv.w;
        }
        __syncthreads();

        float sreg[16];
        #pragma unroll
        for (int i = 0; i < 16; i++) {
            int kk = d0 + i;
            float s = 0.f;
            #pragma unroll
            for (int d = 0; d < 64; d++) s += q_reg[d] * kp_sm[kk][d];
            sreg[i] = ((kt * 64 + kk) <= qrow) ? s : -1e30f;
        }
        __syncthreads();

        float mt = sreg[0];
        #pragma unroll
        for (int i = 1; i < 16; i++) mt = fmaxf(mt, sreg[i]);
        mt = fmaxf(mt, __shfl_xor_sync(0xffffffffu, mt, 1));
        mt = fmaxf(mt, __shfl_xor_sync(0xffffffffu, mt, 2));
        float m_new   = fmaxf(m_i, mt);
        float rescale = __expf(m_i - m_new);

        float psum = 0.f;
        #pragma unroll
        for (int i = 0; i < 16; i++) {
            float p = __expf(sreg[i] - m_new);
            psum += p;
            kp_sm[r][d0 + i] = p;
        }
        psum += __shfl_xor_sync(0xffffffffu, psum, 1);
        psum += __shfl_xor_sync(0xffffffffu, psum, 2);
        l_i = l_i * rescale + psum;
        m_i = m_new;
        #pragma unroll
        for (int j = 0; j < 16; j++) acc[j] *= rescale;
        __syncwarp();

        #pragma unroll 4
        for (int k = 0; k < 64; k++) {
            float p = kp_sm[r][k];
            #pragma unroll
            for (int j = 0; j < 16; j++)
                acc[j] += p * v_sm[k][d0 + j];
        }
    }

    float inv = 1.f / l_i;
    int b = bh >> 4, h = bh & 15;
    float* op = g_ao + (size_t)(b * S_LEN + qrow) * C_DIM + h * D_DIM + d0;
    #pragma unroll
    for (int j = 0; j < 16; j += 4) {
        float4 o = make_float4(acc[j] * inv, acc[j + 1] * inv,
                               acc[j + 2] * inv, acc[j + 3] * inv);
        *(float4*)(op + j) = o;
    }
}

// ---------------------------------------------------------------------------
extern "C" void kernel_launch(void* const* d_in, const int* in_sizes, int n_in,
                              void* d_out, int out_size)
{
    const float* x      = (const float*)d_in[0];
    const float* w_qkv  = (const float*)d_in[1];
    const float* b_qkv  = (const float*)d_in[2];
    const float* w_proj = (const float*)d_in[3];
    const float* b_proj = (const float*)d_in[4];
    float* out = (float*)d_out;

    const int M = B_SZ * S_LEN;  // 8192

    // 1) QKV GEMM + bias (tf32 tensor cores), scattered into [B,H,S,D] q/k/v
    sgemm_tf32_k<0><<<dim3((3 * C_DIM) / 128, M / 128), 256>>>(
        x, w_qkv, b_qkv, nullptr, M, 3 * C_DIM, C_DIM);

    // 2) Causal flash attention -> g_ao in [B,S,C]
    attn_k<<<dim3(S_LEN / 64, BHN), 256>>>();

    // 3) Output projection + bias (tf32 tensor cores)
    sgemm_tf32_k<1><<<dim3(C_DIM / 128, M / 128), 256>>>(
        nullptr, w_proj, b_proj, out, M, C_DIM, C_DIM);
}

// round 3
// speedup vs baseline: 5.2536x; 4.3021x over previous
#include <cuda_runtime.h>
#include <cstdint>

#define B_SZ  4
#define S_LEN 2048
#define C_DIM 1024
#define H_NUM 16
#define D_DIM 64
#define BHN   (B_SZ * H_NUM)

// Scratch: Q,K,V in [B,H,S,D] layout; attention output back in [B,S,C] layout.
__device__ float g_q[BHN * S_LEN * D_DIM];
__device__ float g_k[BHN * S_LEN * D_DIM];
__device__ float g_v[BHN * S_LEN * D_DIM];
__device__ float g_ao[B_SZ * S_LEN * C_DIM];

// ---------------------------------------------------------------------------
// Helpers: cp.async + tf32 mma
// ---------------------------------------------------------------------------
__device__ __forceinline__ void cp_async16(void* smem_dst, const void* gmem_src) {
    uint32_t s = (uint32_t)__cvta_generic_to_shared(smem_dst);
    asm volatile("cp.async.cg.shared.global [%0], [%1], 16;\n" :: "r"(s), "l"(gmem_src));
}
__device__ __forceinline__ void cp_commit() {
    asm volatile("cp.async.commit_group;\n");
}
template <int N>
__device__ __forceinline__ void cp_wait() {
    asm volatile("cp.async.wait_group %0;\n" :: "n"(N));
}
__device__ __forceinline__ uint32_t f2tf32(float f) {
    uint32_t r;
    asm("cvt.rna.tf32.f32 %0, %1;\n" : "=r"(r) : "f"(f));
    return r;
}
__device__ __forceinline__ void mma_tf32(float c[4], const uint32_t a[4], const uint32_t b[2]) {
    asm volatile(
        "mma.sync.aligned.m16n8k8.row.col.f32.tf32.tf32.f32 "
        "{%0,%1,%2,%3}, {%4,%5,%6,%7}, {%8,%9}, {%0,%1,%2,%3};\n"
        : "+f"(c[0]), "+f"(c[1]), "+f"(c[2]), "+f"(c[3])
        : "r"(a[0]), "r"(a[1]), "r"(a[2]), "r"(a[3]), "r"(b[0]), "r"(b[1]));
}

// ---------------------------------------------------------------------------
// TF32 tensor-core GEMM (unchanged from R2): C = A@B + bias
// ---------------------------------------------------------------------------
#define A_STRIDE 20
#define B_STRIDE 136

template <int MODE>
__global__ void __launch_bounds__(256, 2) sgemm_tf32_k(
    const float* __restrict__ A, const float* __restrict__ Bm,
    const float* __restrict__ bias, float* __restrict__ Cout,
    int M, int N, int K)
{
    constexpr int BM = 128, BN = 128, BK = 16;
    __shared__ float As[2][BM * A_STRIDE];
    __shared__ float Bs[2][BK * B_STRIDE];

    const float* Ap = (MODE == 1) ? (const float*)g_ao : A;

    const int tid  = threadIdx.x;
    const int lane = tid & 31;
    const int wid  = tid >> 5;
    const int wm   = wid & 3;
    const int wn   = wid >> 2;
    const int lr   = lane >> 2;
    const int lc   = lane & 3;

    const int rowBlk = blockIdx.y * BM;
    const int colBlk = blockIdx.x * BN;
    const int NK = K / BK;

    auto issue_stage = [&](int buf, int kt) {
        #pragma unroll
        for (int u = 0; u < 2; u++) {
            int c = tid * 2 + u;
            int ar = c >> 2;
            int ak = (c & 3) * 4;
            cp_async16(&As[buf][ar * A_STRIDE + ak],
                       Ap + (size_t)(rowBlk + ar) * K + kt * BK + ak);
            int br = c >> 5;
            int bn = (c & 31) * 4;
            cp_async16(&Bs[buf][br * B_STRIDE + bn],
                       Bm + (size_t)(kt * BK + br) * N + colBlk + bn);
        }
        cp_commit();
    };

    float acc[2][8][4];
    #pragma unroll
    for (int mt = 0; mt < 2; mt++)
        #pragma unroll
        for (int nt = 0; nt < 8; nt++)
            #pragma unroll
            for (int i = 0; i < 4; i++) acc[mt][nt][i] = 0.f;

    issue_stage(0, 0);

    for (int kt = 0; kt < NK; kt++) {
        if (kt + 1 < NK) {
            issue_stage((kt + 1) & 1, kt + 1);
            cp_wait<1>();
        } else {
            cp_wait<0>();
        }
        __syncthreads();

        const float* As_ = As[kt & 1];
        const float* Bs_ = Bs[kt & 1];

        #pragma unroll
        for (int ks = 0; ks < 2; ks++) {
            const int kk = ks * 8;
            uint32_t afr[2][4];
            #pragma unroll
            for (int mt = 0; mt < 2; mt++) {
                int m0 = wm * 32 + mt * 16 + lr;
                afr[mt][0] = f2tf32(As_[m0 * A_STRIDE + kk + lc]);
                afr[mt][1] = f2tf32(As_[(m0 + 8) * A_STRIDE + kk + lc]);
                afr[mt][2] = f2tf32(As_[m0 * A_STRIDE + kk + lc + 4]);
                afr[mt][3] = f2tf32(As_[(m0 + 8) * A_STRIDE + kk + lc + 4]);
            }
            uint32_t bfr[8][2];
            #pragma unroll
            for (int nt = 0; nt < 8; nt++) {
                int n0 = wn * 64 + nt * 8 + lr;
                bfr[nt][0] = f2tf32(Bs_[(kk + lc) * B_STRIDE + n0]);
                bfr[nt][1] = f2tf32(Bs_[(kk + lc + 4) * B_STRIDE + n0]);
            }
            #pragma unroll
            for (int mt = 0; mt < 2; mt++)
                #pragma unroll
                for (int nt = 0; nt < 8; nt++)
                    mma_tf32(acc[mt][nt], afr[mt], bfr[nt]);
        }
        __syncthreads();
    }

    #pragma unroll
    for (int nt = 0; nt < 8; nt++) {
        int col = colBlk + wn * 64 + nt * 8 + lc * 2;
        float2 bb = *(const float2*)(bias + col);
        if (MODE == 0) {
            int which = col / C_DIM;
            int cc    = col % C_DIM;
            int h  = cc / D_DIM;
            int d0 = cc % D_DIM;
            float* dst = (which == 0) ? g_q : (which == 1) ? g_k : g_v;
            #pragma unroll
            for (int mt = 0; mt < 2; mt++) {
                int r0 = rowBlk + wm * 32 + mt * 16 + lr;
                #pragma unroll
                for (int half = 0; half < 2; half++) {
                    int m = r0 + half * 8;
                    int b = m >> 11;
                    int s = m & (S_LEN - 1);
                    float* p = dst + ((size_t)(b * H_NUM + h) * S_LEN + s) * D_DIM + d0;
                    *(float2*)p = make_float2(acc[mt][nt][half * 2 + 0] + bb.x,
                                              acc[mt][nt][half * 2 + 1] + bb.y);
                }
            }
        } else {
            #pragma unroll
            for (int mt = 0; mt < 2; mt++) {
                int r0 = rowBlk + wm * 32 + mt * 16 + lr;
                #pragma unroll
                for (int half = 0; half < 2; half++) {
                    int m = r0 + half * 8;
                    float* p = Cout + (size_t)m * N + col;
                    *(float2*)p = make_float2(acc[mt][nt][half * 2 + 0] + bb.x,
                                              acc[mt][nt][half * 2 + 1] + bb.y);
                }
            }
        }
    }
}

// ---------------------------------------------------------------------------
// Tensor-core causal flash attention.
// Block = one (b,h) x 64-row Q tile. 128 threads = 4 warps; warp w owns
// Q rows [w*16, w*16+16). QK^T via 3xTF32 (fp32-grade scores), PV via tf32.
// SMEM (48KB exactly): Q[64x64], K/P overlay [64x64], V[64x64], XOR-swizzled
// so all fragment LDS are bank-conflict-free:
//   A-side / K-side: elem [row][d] at row*64 + (d ^ (4*(row&7)))
//   V:               elem [k][d]   at k*64   + (d ^ (8*(k&3)))
// ---------------------------------------------------------------------------
__global__ void __launch_bounds__(128) attn_mma_k()
{
    __shared__ float q_sm[64 * 64];
    __shared__ float kp_sm[64 * 64];   // K tile, overlaid by P after scores
    __shared__ float v_sm[64 * 64];

    const int tid  = threadIdx.x;
    const int lane = tid & 31;
    const int w    = tid >> 5;
    const int lr   = lane >> 2;   // 0..7
    const int lc   = lane & 3;    // 0..3
    const int qt   = blockIdx.x;
    const int bh   = blockIdx.y;
    const int m0   = w * 16;

    const float* qb = g_q + (size_t)bh * S_LEN * D_DIM;
    const float* kb = g_k + (size_t)bh * S_LEN * D_DIM;
    const float* vb = g_v + (size_t)bh * S_LEN * D_DIM;

    // Load Q tile (pre-scaled by 1/sqrt(D)), swizzled
    for (int i = tid; i < 64 * 16; i += 128) {
        int row = i >> 4, d0 = (i & 15) * 4;
        float4 qv = *(const float4*)(qb + (size_t)(qt * 64 + row) * D_DIM + d0);
        float* p = &q_sm[row * 64 + (d0 ^ (4 * (row & 7)))];
        p[0] = qv.x * 0.125f; p[1] = qv.y * 0.125f;
        p[2] = qv.z * 0.125f; p[3] = qv.w * 0.125f;
    }
    __syncthreads();

    // Cache this warp's Q fragments (hi + lo tf32 split)
    uint32_t qhi[8][4], qlo[8][4];
    #pragma unroll
    for (int ks = 0; ks < 8; ks++) {
        const int kk = ks * 8;
        const int sw = 4 * lr;
        float x0 = q_sm[(m0 + lr) * 64     + ((kk + lc) ^ sw)];
        float x1 = q_sm[(m0 + lr + 8) * 64 + ((kk + lc) ^ sw)];
        float x2 = q_sm[(m0 + lr) * 64     + ((kk + lc + 4) ^ sw)];
        float x3 = q_sm[(m0 + lr + 8) * 64 + ((kk + lc + 4) ^ sw)];
        qhi[ks][0] = f2tf32(x0); qlo[ks][0] = f2tf32(x0 - __uint_as_float(qhi[ks][0]));
        qhi[ks][1] = f2tf32(x1); qlo[ks][1] = f2tf32(x1 - __uint_as_float(qhi[ks][1]));
        qhi[ks][2] = f2tf32(x2); qlo[ks][2] = f2tf32(x2 - __uint_as_float(qhi[ks][2]));
        qhi[ks][3] = f2tf32(x3); qlo[ks][3] = f2tf32(x3 - __uint_as_float(qhi[ks][3]));
    }

    float m_i[2] = {-1e30f, -1e30f};
    float l_i[2] = {0.f, 0.f};
    float oacc[8][4];
    #pragma unroll
    for (int nt = 0; nt < 8; nt++)
        #pragma unroll
        for (int i = 0; i < 4; i++) oacc[nt][i] = 0.f;

    for (int kt = 0; kt <= qt; kt++) {
        __syncthreads();   // previous PV reads of kp_sm/v_sm complete
        // Load K (A-side swizzle) and V (V swizzle)
        for (int i = tid; i < 64 * 16; i += 128) {
            int row = i >> 4, d0 = (i & 15) * 4;
            size_t base = (size_t)(kt * 64 + row) * D_DIM + d0;
            float4 kv = *(const float4*)(kb + base);
            *(float4*)&kp_sm[row * 64 + (d0 ^ (4 * (row & 7)))] = kv;
            float4 vv = *(const float4*)(vb + base);
            *(float4*)&v_sm[row * 64 + (d0 ^ (8 * (row & 3)))] = vv;
        }
        __syncthreads();

        // S = Q @ K^T via 3xTF32
        float sacc[8][4];
        #pragma unroll
        for (int nt = 0; nt < 8; nt++)
            #pragma unroll
            for (int i = 0; i < 4; i++) sacc[nt][i] = 0.f;

        #pragma unroll
        for (int ks = 0; ks < 8; ks++) {
            const int kk = ks * 8;
            #pragma unroll
            for (int nt = 0; nt < 8; nt++) {
                int krow = nt * 8 + lr;
                int sw   = 4 * lr;           // 4*(krow&7)
                float b0f = kp_sm[krow * 64 + ((kk + lc) ^ sw)];
                float b1f = kp_sm[krow * 64 + ((kk + lc + 4) ^ sw)];
                uint32_t bhi[2], blo[2];
                bhi[0] = f2tf32(b0f); blo[0] = f2tf32(b0f - __uint_as_float(bhi[0]));
                bhi[1] = f2tf32(b1f); blo[1] = f2tf32(b1f - __uint_as_float(bhi[1]));
                mma_tf32(sacc[nt], qhi[ks], bhi);
                mma_tf32(sacc[nt], qlo[ks], bhi);
                mma_tf32(sacc[nt], qhi[ks], blo);
            }
        }

        // Causal mask (only the diagonal tile needs it)
        if (kt == qt) {
            #pragma unroll
            for (int nt = 0; nt < 8; nt++) {
                int c0 = nt * 8 + 2 * lc;
                int r0 = m0 + lr, r1 = r0 + 8;
                if (c0     > r0) sacc[nt][0] = -1e30f;
                if (c0 + 1 > r0) sacc[nt][1] = -1e30f;
                if (c0     > r1) sacc[nt][2] = -1e30f;
                if (c0 + 1 > r1) sacc[nt][3] = -1e30f;
            }
        }

        // Online softmax (rows lr and lr+8; reduce across the 4 lanes of each row)
        float mx0 = -1e30f, mx1 = -1e30f;
        #pragma unroll
        for (int nt = 0; nt < 8; nt++) {
            mx0 = fmaxf(mx0, fmaxf(sacc[nt][0], sacc[nt][1]));
            mx1 = fmaxf(mx1, fmaxf(sacc[nt][2], sacc[nt][3]));
        }
        mx0 = fmaxf(mx0, __shfl_xor_sync(0xffffffffu, mx0, 1));
        mx0 = fmaxf(mx0, __shfl_xor_sync(0xffffffffu, mx0, 2));
        mx1 = fmaxf(mx1, __shfl_xor_sync(0xffffffffu, mx1, 1));
        mx1 = fmaxf(mx1, __shfl_xor_sync(0xffffffffu, mx1, 2));
        float mn0 = fmaxf(m_i[0], mx0);
        float mn1 = fmaxf(m_i[1], mx1);
        float rs0 = __expf(m_i[0] - mn0);
        float rs1 = __expf(m_i[1] - mn1);

        float sum0 = 0.f, sum1 = 0.f;
        #pragma unroll
        for (int nt = 0; nt < 8; nt++) {
            sacc[nt][0] = __expf(sacc[nt][0] - mn0); sum0 += sacc[nt][0];
            sacc[nt][1] = __expf(sacc[nt][1] - mn0); sum0 += sacc[nt][1];
            sacc[nt][2] = __expf(sacc[nt][2] - mn1); sum1 += sacc[nt][2];
            sacc[nt][3] = __expf(sacc[nt][3] - mn1); sum1 += sacc[nt][3];
        }
        sum0 += __shfl_xor_sync(0xffffffffu, sum0, 1);
        sum0 += __shfl_xor_sync(0xffffffffu, sum0, 2);
        sum1 += __shfl_xor_sync(0xffffffffu, sum1, 1);
        sum1 += __shfl_xor_sync(0xffffffffu, sum1, 2);
        l_i[0] = l_i[0] * rs0 + sum0;
        l_i[1] = l_i[1] * rs1 + sum1;
        m_i[0] = mn0; m_i[1] = mn1;
        #pragma unroll
        for (int nt = 0; nt < 8; nt++) {
            oacc[nt][0] *= rs0; oacc[nt][1] *= rs0;
            oacc[nt][2] *= rs1; oacc[nt][3] *= rs1;
        }

        __syncthreads();   // all warps done reading K before P overlay

        // Store P into kp_sm (A-side swizzle); this warp's own rows only
        #pragma unroll
        for (int nt = 0; nt < 8; nt++) {
            int c0 = nt * 8 + 2 * lc;
            int sw = 4 * lr;   // (m0+lr[+8]) & 7 == lr
            *(float2*)&kp_sm[(m0 + lr) * 64     + (c0 ^ sw)] =
                make_float2(sacc[nt][0], sacc[nt][1]);
            *(float2*)&kp_sm[(m0 + lr + 8) * 64 + (c0 ^ sw)] =
                make_float2(sacc[nt][2], sacc[nt][3]);
        }
        __syncwarp();      // PV A-frags read only this warp's rows

        // O += P @ V  (tf32)
        #pragma unroll
        for (int ks = 0; ks < 8; ks++) {
            const int kk = ks * 8;
            const int sw = 4 * lr;
            uint32_t pa[4];
            pa[0] = f2tf32(kp_sm[(m0 + lr) * 64     + ((kk + lc) ^ sw)]);
            pa[1] = f2tf32(kp_sm[(m0 + lr + 8) * 64 + ((kk + lc) ^ sw)]);
            pa[2] = f2tf32(kp_sm[(m0 + lr) * 64     + ((kk + lc + 4) ^ sw)]);
            pa[3] = f2tf32(kp_sm[(m0 + lr + 8) * 64 + ((kk + lc + 4) ^ sw)]);
            #pragma unroll
            for (int nt = 0; nt < 8; nt++) {
                int k0 = kk + lc;
                int vsw = 8 * (k0 & 3);   // (k0+4)&3 == k0&3
                uint32_t vb2[2];
                vb2[0] = f2tf32(v_sm[k0 * 64       + ((nt * 8 + lr) ^ vsw)]);
                vb2[1] = f2tf32(v_sm[(k0 + 4) * 64 + ((nt * 8 + lr) ^ vsw)]);
                mma_tf32(oacc[nt], pa, vb2);
            }
        }
    }

    // Epilogue: normalize and write to g_ao [B,S,C]
    float inv0 = 1.f / l_i[0];
    float inv1 = 1.f / l_i[1];
    int b = bh >> 4, h = bh & 15;
    #pragma unroll
    for (int nt = 0; nt < 8; nt++) {
        int d = nt * 8 + 2 * lc;
        int i0 = qt * 64 + m0 + lr;
        float* p0 = g_ao + (size_t)(b * S_LEN + i0) * C_DIM + h * D_DIM + d;
        *(float2*)p0 = make_float2(oacc[nt][0] * inv0, oacc[nt][1] * inv0);
        float* p1 = g_ao + (size_t)(b * S_LEN + i0 + 8) * C_DIM + h * D_DIM + d;
        *(float2*)p1 = make_float2(oacc[nt][2] * inv1, oacc[nt][3] * inv1);
    }
}

// ---------------------------------------------------------------------------
extern "C" void kernel_launch(void* const* d_in, const int* in_sizes, int n_in,
                              void* d_out, int out_size)
{
    const float* x      = (const float*)d_in[0];
    const float* w_qkv  = (const float*)d_in[1];
    const float* b_qkv  = (const float*)d_in[2];
    const float* w_proj = (const float*)d_in[3];
    const float* b_proj = (const float*)d_in[4];
    float* out = (float*)d_out;

    const int M = B_SZ * S_LEN;  // 8192

    sgemm_tf32_k<0><<<dim3((3 * C_DIM) / 128, M / 128), 256>>>(
        x, w_qkv, b_qkv, nullptr, M, 3 * C_DIM, C_DIM);

    attn_mma_k<<<dim3(S_LEN / 64, BHN), 128>>>();

    sgemm_tf32_k<1><<<dim3(C_DIM / 128, M / 128), 256>>>(
        nullptr, w_proj, b_proj, out, M, C_DIM, C_DIM);
}

// round 5
// speedup vs baseline: 5.3047x; 1.0097x over previous
#include <cuda_runtime.h>
#include <cstdint>

#define B_SZ  4
#define S_LEN 2048
#define C_DIM 1024
#define H_NUM 16
#define D_DIM 64
#define BHN   (B_SZ * H_NUM)

// Scratch (device-symbol addresses must only be taken in DEVICE code)
__device__ float g_q[BHN * S_LEN * D_DIM];
__device__ float g_k[BHN * S_LEN * D_DIM];
__device__ float g_v[BHN * S_LEN * D_DIM];
__device__ float g_ao[B_SZ * S_LEN * C_DIM];     // attention out, tf32-rounded
__device__ float g_xr[B_SZ * S_LEN * C_DIM];     // tf32-rounded x
__device__ float g_wqkvr[C_DIM * 3 * C_DIM];     // tf32-rounded w_qkv
__device__ float g_wprojr[C_DIM * C_DIM];        // tf32-rounded w_proj

// ---------------------------------------------------------------------------
__device__ __forceinline__ void cp_async16(void* smem_dst, const void* gmem_src) {
    uint32_t s = (uint32_t)__cvta_generic_to_shared(smem_dst);
    asm volatile("cp.async.cg.shared.global [%0], [%1], 16;\n" :: "r"(s), "l"(gmem_src));
}
__device__ __forceinline__ void cp_commit() {
    asm volatile("cp.async.commit_group;\n");
}
template <int N>
__device__ __forceinline__ void cp_wait() {
    asm volatile("cp.async.wait_group %0;\n" :: "n"(N));
}
__device__ __forceinline__ uint32_t f2tf32(float f) {
    uint32_t r;
    asm("cvt.rna.tf32.f32 %0, %1;\n" : "=r"(r) : "f"(f));
    return r;
}
__device__ __forceinline__ float rnd_tf32(float f) {
    return __uint_as_float(f2tf32(f));
}
__device__ __forceinline__ void mma_tf32(float c[4], const uint32_t a[4], const uint32_t b[2]) {
    asm volatile(
        "mma.sync.aligned.m16n8k8.row.col.f32.tf32.tf32.f32 "
        "{%0,%1,%2,%3}, {%4,%5,%6,%7}, {%8,%9}, {%0,%1,%2,%3};\n"
        : "+f"(c[0]), "+f"(c[1]), "+f"(c[2]), "+f"(c[3])
        : "r"(a[0]), "r"(a[1]), "r"(a[2]), "r"(a[3]), "r"(b[0]), "r"(b[1]));
}

// ---------------------------------------------------------------------------
// Elementwise RNA-round to tf32. DST selects the __device__ destination
// inside device code (host must not touch device symbols).
// DST: 0 -> g_xr, 1 -> g_wqkvr, 2 -> g_wprojr
// ---------------------------------------------------------------------------
template <int DST>
__global__ void round_tf32_k(const float* __restrict__ src, int n4)
{
    float* dst = (DST == 0) ? g_xr : (DST == 1) ? g_wqkvr : g_wprojr;
    int i = blockIdx.x * blockDim.x + threadIdx.x;
    if (i < n4) {
        float4 v = ((const float4*)src)[i];
        v.x = rnd_tf32(v.x); v.y = rnd_tf32(v.y);
        v.z = rnd_tf32(v.z); v.w = rnd_tf32(v.w);
        ((float4*)dst)[i] = v;
    }
}

// ---------------------------------------------------------------------------
// TF32 tensor-core GEMM, pre-rounded operands -> raw-bit fragments (no cvt).
// MODE 0: A = g_xr, B = g_wqkvr, epilogue scatters to g_q/g_k/g_v
// MODE 1: A = g_ao, B = g_wprojr, epilogue writes Cout
// ---------------------------------------------------------------------------
#define A_STRIDE 20
#define B_STRIDE 136

template <int MODE>
__global__ void __launch_bounds__(256, 2) sgemm_tf32_k(
    const float* __restrict__ bias, float* __restrict__ Cout,
    int M, int N, int K)
{
    constexpr int BM = 128, BK = 16;
    __shared__ float As[2][BM * A_STRIDE];
    __shared__ float Bs[2][BK * B_STRIDE];

    const float* A  = (MODE == 0) ? g_xr    : g_ao;
    const float* Bm = (MODE == 0) ? g_wqkvr : g_wprojr;

    const int tid  = threadIdx.x;
    const int lane = tid & 31;
    const int wid  = tid >> 5;
    const int wm   = wid & 3;
    const int wn   = wid >> 2;
    const int lr   = lane >> 2;
    const int lc   = lane & 3;

    const int rowBlk = blockIdx.y * BM;
    const int colBlk = blockIdx.x * 128;
    const int NK = K / BK;

    auto issue_stage = [&](int buf, int kt) {
        #pragma unroll
        for (int u = 0; u < 2; u++) {
            int c = tid * 2 + u;
            int ar = c >> 2;
            int ak = (c & 3) * 4;
            cp_async16(&As[buf][ar * A_STRIDE + ak],
                       A + (size_t)(rowBlk + ar) * K + kt * BK + ak);
            int br = c >> 5;
            int bn = (c & 31) * 4;
            cp_async16(&Bs[buf][br * B_STRIDE + bn],
                       Bm + (size_t)(kt * BK + br) * N + colBlk + bn);
        }
        cp_commit();
    };

    float acc[2][8][4];
    #pragma unroll
    for (int mt = 0; mt < 2; mt++)
        #pragma unroll
        for (int nt = 0; nt < 8; nt++)
            #pragma unroll
            for (int i = 0; i < 4; i++) acc[mt][nt][i] = 0.f;

    issue_stage(0, 0);

    for (int kt = 0; kt < NK; kt++) {
        if (kt + 1 < NK) {
            issue_stage((kt + 1) & 1, kt + 1);
            cp_wait<1>();
        } else {
            cp_wait<0>();
        }
        __syncthreads();

        const uint32_t* As_ = (const uint32_t*)As[kt & 1];
        const uint32_t* Bs_ = (const uint32_t*)Bs[kt & 1];

        #pragma unroll
        for (int ks = 0; ks < 2; ks++) {
            const int kk = ks * 8;
            uint32_t afr[2][4];
            #pragma unroll
            for (int mt = 0; mt < 2; mt++) {
                int m0 = wm * 32 + mt * 16 + lr;
                afr[mt][0] = As_[m0 * A_STRIDE + kk + lc];
                afr[mt][1] = As_[(m0 + 8) * A_STRIDE + kk + lc];
                afr[mt][2] = As_[m0 * A_STRIDE + kk + lc + 4];
                afr[mt][3] = As_[(m0 + 8) * A_STRIDE + kk + lc + 4];
            }
            uint32_t bfr[8][2];
            #pragma unroll
            for (int nt = 0; nt < 8; nt++) {
                int n0 = wn * 64 + nt * 8 + lr;
                bfr[nt][0] = Bs_[(kk + lc) * B_STRIDE + n0];
                bfr[nt][1] = Bs_[(kk + lc + 4) * B_STRIDE + n0];
            }
            #pragma unroll
            for (int mt = 0; mt < 2; mt++)
                #pragma unroll
                for (int nt = 0; nt < 8; nt++)
                    mma_tf32(acc[mt][nt], afr[mt], bfr[nt]);
        }
        __syncthreads();
    }

    #pragma unroll
    for (int nt = 0; nt < 8; nt++) {
        int col = colBlk + wn * 64 + nt * 8 + lc * 2;
        float2 bb = *(const float2*)(bias + col);
        if (MODE == 0) {
            int which = col / C_DIM;
            int cc    = col % C_DIM;
            int h  = cc / D_DIM;
            int d0 = cc % D_DIM;
            float* dst = (which == 0) ? g_q : (which == 1) ? g_k : g_v;
            #pragma unroll
            for (int mt = 0; mt < 2; mt++) {
                int r0 = rowBlk + wm * 32 + mt * 16 + lr;
                #pragma unroll
                for (int half = 0; half < 2; half++) {
                    int m = r0 + half * 8;
                    int b = m >> 11;
                    int s = m & (S_LEN - 1);
                    float* p = dst + ((size_t)(b * H_NUM + h) * S_LEN + s) * D_DIM + d0;
                    *(float2*)p = make_float2(acc[mt][nt][half * 2 + 0] + bb.x,
                                              acc[mt][nt][half * 2 + 1] + bb.y);
                }
            }
        } else {
            #pragma unroll
            for (int mt = 0; mt < 2; mt++) {
                int r0 = rowBlk + wm * 32 + mt * 16 + lr;
                #pragma unroll
                for (int half = 0; half < 2; half++) {
                    int m = r0 + half * 8;
                    float* p = Cout + (size_t)m * N + col;
                    *(float2*)p = make_float2(acc[mt][nt][half * 2 + 0] + bb.x,
                                              acc[mt][nt][half * 2 + 1] + bb.y);
                }
            }
        }
    }
}

// ---------------------------------------------------------------------------
// Tensor-core causal flash attention, conversion-free inner loops.
// Block = (b,h) x 64-row Q tile; 4 warps, warp w owns rows [w*16, w*16+16).
// SMEM 48KB: klo_sm (Q staging -> K-lo), kp_sm (K-hi -> P), v_sm (V rounded).
// Swizzles: A/K-side row*64 + (d ^ 4*(row&7)); V k*64 + (d ^ 8*(k&3)).
// ---------------------------------------------------------------------------
__global__ void __launch_bounds__(128) attn_mma_k()
{
    __shared__ float klo_sm[64 * 64];
    __shared__ float kp_sm[64 * 64];
    __shared__ float v_sm[64 * 64];

    const int tid  = threadIdx.x;
    const int lane = tid & 31;
    const int w    = tid >> 5;
    const int lr   = lane >> 2;
    const int lc   = lane & 3;
    const int qt   = blockIdx.x;
    const int bh   = blockIdx.y;
    const int m0   = w * 16;

    const float* qb = g_q + (size_t)bh * S_LEN * D_DIM;
    const float* kb = g_k + (size_t)bh * S_LEN * D_DIM;
    const float* vb = g_v + (size_t)bh * S_LEN * D_DIM;

    // Stage Q (scaled), extract hi/lo fragments, then klo_sm is reusable
    for (int i = tid; i < 64 * 16; i += 128) {
        int row = i >> 4, d0 = (i & 15) * 4;
        float4 qv = *(const float4*)(qb + (size_t)(qt * 64 + row) * D_DIM + d0);
        float* p = &klo_sm[row * 64 + (d0 ^ (4 * (row & 7)))];
        p[0] = qv.x * 0.125f; p[1] = qv.y * 0.125f;
        p[2] = qv.z * 0.125f; p[3] = qv.w * 0.125f;
    }
    __syncthreads();

    uint32_t qhi[8][4], qlo[8][4];
    #pragma unroll
    for (int ks = 0; ks < 8; ks++) {
        const int kk = ks * 8;
        const int sw = 4 * lr;
        float x0 = klo_sm[(m0 + lr) * 64     + ((kk + lc) ^ sw)];
        float x1 = klo_sm[(m0 + lr + 8) * 64 + ((kk + lc) ^ sw)];
        float x2 = klo_sm[(m0 + lr) * 64     + ((kk + lc + 4) ^ sw)];
        float x3 = klo_sm[(m0 + lr + 8) * 64 + ((kk + lc + 4) ^ sw)];
        qhi[ks][0] = f2tf32(x0); qlo[ks][0] = f2tf32(x0 - __uint_as_float(qhi[ks][0]));
        qhi[ks][1] = f2tf32(x1); qlo[ks][1] = f2tf32(x1 - __uint_as_float(qhi[ks][1]));
        qhi[ks][2] = f2tf32(x2); qlo[ks][2] = f2tf32(x2 - __uint_as_float(qhi[ks][2]));
        qhi[ks][3] = f2tf32(x3); qlo[ks][3] = f2tf32(x3 - __uint_as_float(qhi[ks][3]));
    }

    float m_i[2] = {-1e30f, -1e30f};
    float l_i[2] = {0.f, 0.f};
    float oacc[8][4];
    #pragma unroll
    for (int nt = 0; nt < 8; nt++)
        #pragma unroll
        for (int i = 0; i < 4; i++) oacc[nt][i] = 0.f;

    for (int kt = 0; kt <= qt; kt++) {
        __syncthreads();
        for (int i = tid; i < 64 * 16; i += 128) {
            int row = i >> 4, d0 = (i & 15) * 4;
            size_t base = (size_t)(kt * 64 + row) * D_DIM + d0;
            float4 kv = *(const float4*)(kb + base);
            float4 hi, lo;
            hi.x = rnd_tf32(kv.x); lo.x = rnd_tf32(kv.x - hi.x);
            hi.y = rnd_tf32(kv.y); lo.y = rnd_tf32(kv.y - hi.y);
            hi.z = rnd_tf32(kv.z); lo.z = rnd_tf32(kv.z - hi.z);
            hi.w = rnd_tf32(kv.w); lo.w = rnd_tf32(kv.w - hi.w);
            int off = row * 64 + (d0 ^ (4 * (row & 7)));
            *(float4*)&kp_sm[off]  = hi;
            *(float4*)&klo_sm[off] = lo;
            float4 vv = *(const float4*)(vb + base);
            vv.x = rnd_tf32(vv.x); vv.y = rnd_tf32(vv.y);
            vv.z = rnd_tf32(vv.z); vv.w = rnd_tf32(vv.w);
            *(float4*)&v_sm[row * 64 + (d0 ^ (8 * (row & 3)))] = vv;
        }
        __syncthreads();

        float sacc[8][4];
        #pragma unroll
        for (int nt = 0; nt < 8; nt++)
            #pragma unroll
            for (int i = 0; i < 4; i++) sacc[nt][i] = 0.f;

        #pragma unroll
        for (int ks = 0; ks < 8; ks++) {
            const int kk = ks * 8;
            #pragma unroll
            for (int nt = 0; nt < 8; nt++) {
                int krow = nt * 8 + lr;
                int sw   = 4 * lr;
                int o0 = krow * 64 + ((kk + lc) ^ sw);
                int o1 = krow * 64 + ((kk + lc + 4) ^ sw);
                uint32_t bhi[2], blo[2];
                bhi[0] = __float_as_uint(kp_sm[o0]);
                bhi[1] = __float_as_uint(kp_sm[o1]);
                blo[0] = __float_as_uint(klo_sm[o0]);
                blo[1] = __float_as_uint(klo_sm[o1]);
                mma_tf32(sacc[nt], qhi[ks], bhi);
                mma_tf32(sacc[nt], qlo[ks], bhi);
                mma_tf32(sacc[nt], qhi[ks], blo);
            }
        }

        if (kt == qt) {
            #pragma unroll
            for (int nt = 0; nt < 8; nt++) {
                int c0 = nt * 8 + 2 * lc;
                int r0 = m0 + lr, r1 = r0 + 8;
                if (c0     > r0) sacc[nt][0] = -1e30f;
                if (c0 + 1 > r0) sacc[nt][1] = -1e30f;
                if (c0     > r1) sacc[nt][2] = -1e30f;
                if (c0 + 1 > r1) sacc[nt][3] = -1e30f;
            }
        }

        float mx0 = -1e30f, mx1 = -1e30f;
        #pragma unroll
        for (int nt = 0; nt < 8; nt++) {
            mx0 = fmaxf(mx0, fmaxf(sacc[nt][0], sacc[nt][1]));
            mx1 = fmaxf(mx1, fmaxf(sacc[nt][2], sacc[nt][3]));
        }
        mx0 = fmaxf(mx0, __shfl_xor_sync(0xffffffffu, mx0, 1));
        mx0 = fmaxf(mx0, __shfl_xor_sync(0xffffffffu, mx0, 2));
        mx1 = fmaxf(mx1, __shfl_xor_sync(0xffffffffu, mx1, 1));
        mx1 = fmaxf(mx1, __shfl_xor_sync(0xffffffffu, mx1, 2));
        float mn0 = fmaxf(m_i[0], mx0);
        float mn1 = fmaxf(m_i[1], mx1);
        float rs0 = __expf(m_i[0] - mn0);
        float rs1 = __expf(m_i[1] - mn1);

        float sum0 = 0.f, sum1 = 0.f;
        #pragma unroll
        for (int nt = 0; nt < 8; nt++) {
            sacc[nt][0] = __expf(sacc[nt][0] - mn0); sum0 += sacc[nt][0];
            sacc[nt][1] = __expf(sacc[nt][1] - mn0); sum0 += sacc[nt][1];
            sacc[nt][2] = __expf(sacc[nt][2] - mn1); sum1 += sacc[nt][2];
            sacc[nt][3] = __expf(sacc[nt][3] - mn1); sum1 += sacc[nt][3];
        }
        sum0 += __shfl_xor_sync(0xffffffffu, sum0, 1);
        sum0 += __shfl_xor_sync(0xffffffffu, sum0, 2);
        sum1 += __shfl_xor_sync(0xffffffffu, sum1, 1);
        sum1 += __shfl_xor_sync(0xffffffffu, sum1, 2);
        l_i[0] = l_i[0] * rs0 + sum0;
        l_i[1] = l_i[1] * rs1 + sum1;
        m_i[0] = mn0; m_i[1] = mn1;
        #pragma unroll
        for (int nt = 0; nt < 8; nt++) {
            oacc[nt][0] *= rs0; oacc[nt][1] *= rs0;
            oacc[nt][2] *= rs1; oacc[nt][3] *= rs1;
        }

        __syncthreads();

        #pragma unroll
        for (int nt = 0; nt < 8; nt++) {
            int c0 = nt * 8 + 2 * lc;
            int sw = 4 * lr;
            *(float2*)&kp_sm[(m0 + lr) * 64     + (c0 ^ sw)] =
                make_float2(rnd_tf32(sacc[nt][0]), rnd_tf32(sacc[nt][1]));
            *(float2*)&kp_sm[(m0 + lr + 8) * 64 + (c0 ^ sw)] =
                make_float2(rnd_tf32(sacc[nt][2]), rnd_tf32(sacc[nt][3]));
        }
        __syncwarp();

        #pragma unroll
        for (int ks = 0; ks < 8; ks++) {
            const int kk = ks * 8;
            const int sw = 4 * lr;
            uint32_t pa[4];
            pa[0] = __float_as_uint(kp_sm[(m0 + lr) * 64     + ((kk + lc) ^ sw)]);
            pa[1] = __float_as_uint(kp_sm[(m0 + lr + 8) * 64 + ((kk + lc) ^ sw)]);
            pa[2] = __float_as_uint(kp_sm[(m0 + lr) * 64     + ((kk + lc + 4) ^ sw)]);
            pa[3] = __float_as_uint(kp_sm[(m0 + lr + 8) * 64 + ((kk + lc + 4) ^ sw)]);
            #pragma unroll
            for (int nt = 0; nt < 8; nt++) {
                int k0 = kk + lc;
                int vsw = 8 * (k0 & 3);
                uint32_t vb2[2];
                vb2[0] = __float_as_uint(v_sm[k0 * 64       + ((nt * 8 + lr) ^ vsw)]);
                vb2[1] = __float_as_uint(v_sm[(k0 + 4) * 64 + ((nt * 8 + lr) ^ vsw)]);
                mma_tf32(oacc[nt], pa, vb2);
            }
        }
    }

    // Epilogue: normalize, tf32-round (proj GEMM A-side), write g_ao [B,S,C]
    float inv0 = 1.f / l_i[0];
    float inv1 = 1.f / l_i[1];
    int b = bh >> 4, h = bh & 15;
    #pragma unroll
    for (int nt = 0; nt < 8; nt++) {
        int d = nt * 8 + 2 * lc;
        int i0 = qt * 64 + m0 + lr;
        float* p0 = g_ao + (size_t)(b * S_LEN + i0) * C_DIM + h * D_DIM + d;
        *(float2*)p0 = make_float2(rnd_tf32(oacc[nt][0] * inv0),
                                   rnd_tf32(oacc[nt][1] * inv0));
        float* p1 = g_ao + (size_t)(b * S_LEN + i0 + 8) * C_DIM + h * D_DIM + d;
        *(float2*)p1 = make_float2(rnd_tf32(oacc[nt][2] * inv1),
                                   rnd_tf32(oacc[nt][3] * inv1));
    }
}

// ---------------------------------------------------------------------------
extern "C" void kernel_launch(void* const* d_in, const int* in_sizes, int n_in,
                              void* d_out, int out_size)
{
    const float* x      = (const float*)d_in[0];
    const float* w_qkv  = (const float*)d_in[1];
    const float* b_qkv  = (const float*)d_in[2];
    const float* w_proj = (const float*)d_in[3];
    const float* b_proj = (const float*)d_in[4];
    float* out = (float*)d_out;

    const int M = B_SZ * S_LEN;  // 8192

    // 0) Pre-round inputs to tf32 (destinations resolved in device code)
    {
        int n4x = (M * C_DIM) / 4;
        round_tf32_k<0><<<(n4x + 255) / 256, 256>>>(x, n4x);
        int n4w = (C_DIM * 3 * C_DIM) / 4;
        round_tf32_k<1><<<(n4w + 255) / 256, 256>>>(w_qkv, n4w);
        int n4p = (C_DIM * C_DIM) / 4;
        round_tf32_k<2><<<(n4p + 255) / 256, 256>>>(w_proj, n4p);
    }

    // 1) QKV GEMM + bias -> q/k/v [B,H,S,D]
    sgemm_tf32_k<0><<<dim3((3 * C_DIM) / 128, M / 128), 256>>>(
        b_qkv, nullptr, M, 3 * C_DIM, C_DIM);

    // 2) Causal flash attention -> g_ao (tf32-rounded)
    attn_mma_k<<<dim3(S_LEN / 64, BHN), 128>>>();

    // 3) Output projection + bias
    sgemm_tf32_k<1><<<dim3(C_DIM / 128, M / 128), 256>>>(
        b_proj, out, M, C_DIM, C_DIM);
}

// round 6
// speedup vs baseline: 6.0816x; 1.1464x over previous
#include <cuda_runtime.h>
#include <cstdint>

#define B_SZ  4
#define S_LEN 2048
#define C_DIM 1024
#define H_NUM 16
#define D_DIM 64
#define BHN   (B_SZ * H_NUM)
#define M_DIM (B_SZ * S_LEN)   // 8192

// Scratch (__device__ symbols: addresses taken ONLY in device code)
__device__ float g_q  [BHN * S_LEN * D_DIM];   // pre-scaled (x 1/8) fp32 Q
__device__ float g_khi[BHN * S_LEN * D_DIM];   // tf32 hi part of K
__device__ float g_klo[BHN * S_LEN * D_DIM];   // tf32 lo part of K
__device__ float g_v  [BHN * S_LEN * D_DIM];   // tf32-rounded V
__device__ float g_aoT[C_DIM * M_DIM];         // attn out, TRANSPOSED [C][M], tf32-rounded
__device__ float g_xrT[C_DIM * M_DIM];         // x, rounded + transposed [C][M]
__device__ float g_wqkvr[C_DIM * 3 * C_DIM];   // rounded w_qkv
__device__ float g_wprojr[C_DIM * C_DIM];      // rounded w_proj

// ---------------------------------------------------------------------------
__device__ __forceinline__ void cp_async16(void* smem_dst, const void* gmem_src) {
    uint32_t s = (uint32_t)__cvta_generic_to_shared(smem_dst);
    asm volatile("cp.async.cg.shared.global [%0], [%1], 16;\n" :: "r"(s), "l"(gmem_src));
}
__device__ __forceinline__ void cp_commit() {
    asm volatile("cp.async.commit_group;\n");
}
template <int N>
__device__ __forceinline__ void cp_wait() {
    asm volatile("cp.async.wait_group %0;\n" :: "n"(N));
}
__device__ __forceinline__ uint32_t f2tf32(float f) {
    uint32_t r;
    asm("cvt.rna.tf32.f32 %0, %1;\n" : "=r"(r) : "f"(f));
    return r;
}
__device__ __forceinline__ float rnd_tf32(float f) {
    return __uint_as_float(f2tf32(f));
}
__device__ __forceinline__ void mma_tf32(float c[4], const uint32_t a[4], const uint32_t b[2]) {
    asm volatile(
        "mma.sync.aligned.m16n8k8.row.col.f32.tf32.tf32.f32 "
        "{%0,%1,%2,%3}, {%4,%5,%6,%7}, {%8,%9}, {%0,%1,%2,%3};\n"
        : "+f"(c[0]), "+f"(c[1]), "+f"(c[2]), "+f"(c[3])
        : "r"(a[0]), "r"(a[1]), "r"(a[2]), "r"(a[3]), "r"(b[0]), "r"(b[1]));
}

// ---------------------------------------------------------------------------
// Prep kernels
// ---------------------------------------------------------------------------
// x [M][C] -> g_xrT [C][M], tf32-rounded. 256 threads, 32x32 tiles.
__global__ void round_transpose_x_k(const float* __restrict__ x)
{
    __shared__ float t[32][33];
    int bx = blockIdx.x * 32;           // m
    int by = blockIdx.y * 32;           // c
    int tx = threadIdx.x & 31, ty = threadIdx.x >> 5;  // 32 x 8
    #pragma unroll
    for (int i = 0; i < 32; i += 8)
        t[ty + i][tx] = x[(size_t)(bx + ty + i) * C_DIM + by + tx];
    __syncthreads();
    #pragma unroll
    for (int i = 0; i < 32; i += 8)
        g_xrT[(size_t)(by + ty + i) * M_DIM + bx + tx] = rnd_tf32(t[tx][ty + i]);
}

// weight rounding. DST: 1 -> g_wqkvr, 2 -> g_wprojr
template <int DST>
__global__ void round_w_k(const float* __restrict__ src, int n4)
{
    float* dst = (DST == 1) ? g_wqkvr : g_wprojr;
    int i = blockIdx.x * blockDim.x + threadIdx.x;
    if (i < n4) {
        float4 v = ((const float4*)src)[i];
        v.x = rnd_tf32(v.x); v.y = rnd_tf32(v.y);
        v.z = rnd_tf32(v.z); v.w = rnd_tf32(v.w);
        ((float4*)dst)[i] = v;
    }
}

// ---------------------------------------------------------------------------
// TF32 GEMM: C[M,N] = AT^T @ B + bias. AT is [K][M] (pre-rounded tf32 bits).
// BM=BN=128, BK=16, 256 threads (8 warps 4x2), 3-stage cp.async ring,
// ONE __syncthreads per k-tile. Tiles 16x128, XOR swizzle col^(8*(k&3)),
// zero padding -> 3 stages x 2 tiles x 8KB = 48KB static smem.
// MODE 0: AT=g_xrT, B=g_wqkvr; epilogue -> g_q (x1/8), g_khi/g_klo, g_v
// MODE 1: AT=g_aoT, B=g_wprojr; epilogue -> Cout row-major
// ---------------------------------------------------------------------------
template <int MODE>
__global__ void __launch_bounds__(256, 2) sgemm_tf32_k(
    const float* __restrict__ bias, float* __restrict__ Cout, int N)
{
    constexpr int K = C_DIM, BK = 16, NK = K / BK;
    __shared__ float As[3][BK * 128];
    __shared__ float Bs[3][BK * 128];

    const float* AT = (MODE == 0) ? g_xrT   : g_aoT;
    const float* Bm = (MODE == 0) ? g_wqkvr : g_wprojr;

    const int tid  = threadIdx.x;
    const int lane = tid & 31;
    const int wid  = tid >> 5;
    const int wm   = wid & 3;
    const int wn   = wid >> 2;
    const int lr   = lane >> 2;
    const int lc   = lane & 3;

    const int rowBlk = blockIdx.y * 128;
    const int colBlk = blockIdx.x * 128;

    auto issue_stage = [&](int stg, int kt) {
        #pragma unroll
        for (int u = 0; u < 2; u++) {
            int c = tid * 2 + u;          // 0..511
            int row  = c >> 5;            // 0..15
            int col4 = (c & 31) * 4;      // 0..124
            int sw   = col4 ^ (8 * (row & 3));
            cp_async16(&As[stg][row * 128 + sw],
                       AT + (size_t)(kt * BK + row) * M_DIM + rowBlk + col4);
            cp_async16(&Bs[stg][row * 128 + sw],
                       Bm + (size_t)(kt * BK + row) * N + colBlk + col4);
        }
        cp_commit();
    };

    float acc[2][8][4];
    #pragma unroll
    for (int mt = 0; mt < 2; mt++)
        #pragma unroll
        for (int nt = 0; nt < 8; nt++)
            #pragma unroll
            for (int i = 0; i < 4; i++) acc[mt][nt][i] = 0.f;

    issue_stage(0, 0);
    issue_stage(1, 1);

    int stg = 0;
    for (int kt = 0; kt < NK; kt++) {
        if (kt + 1 < NK) cp_wait<1>(); else cp_wait<0>();
        __syncthreads();

        const uint32_t* As_ = (const uint32_t*)As[stg];
        const uint32_t* Bs_ = (const uint32_t*)Bs[stg];

        #pragma unroll
        for (int ks = 0; ks < 2; ks++) {
            const int kk = ks * 8;
            uint32_t afr[2][4];
            #pragma unroll
            for (int mt = 0; mt < 2; mt++) {
                int m0 = wm * 32 + mt * 16 + lr;
                int r0 = kk + lc, r1 = kk + lc + 4;   // r1&3 == r0&3
                int s  = 8 * (r0 & 3);
                afr[mt][0] = As_[r0 * 128 + (m0 ^ s)];
                afr[mt][1] = As_[r0 * 128 + ((m0 + 8) ^ s)];
                afr[mt][2] = As_[r1 * 128 + (m0 ^ s)];
                afr[mt][3] = As_[r1 * 128 + ((m0 + 8) ^ s)];
            }
            uint32_t bfr[8][2];
            #pragma unroll
            for (int nt = 0; nt < 8; nt++) {
                int n0 = wn * 64 + nt * 8 + lr;
                int r0 = kk + lc, r1 = kk + lc + 4;
                int s  = 8 * (r0 & 3);
                bfr[nt][0] = Bs_[r0 * 128 + (n0 ^ s)];
                bfr[nt][1] = Bs_[r1 * 128 + (n0 ^ s)];
            }
            #pragma unroll
            for (int mt = 0; mt < 2; mt++)
                #pragma unroll
                for (int nt = 0; nt < 8; nt++)
                    mma_tf32(acc[mt][nt], afr[mt], bfr[nt]);
        }

        if (kt + 2 < NK) issue_stage((stg + 2) % 3, kt + 2);
        stg = (stg + 1) % 3;
    }

    #pragma unroll
    for (int nt = 0; nt < 8; nt++) {
        int col = colBlk + wn * 64 + nt * 8 + lc * 2;
        float2 bb = *(const float2*)(bias + col);
        if (MODE == 0) {
            int which = col / C_DIM;            // 0=q 1=k 2=v
            int cc    = col % C_DIM;
            int h  = cc / D_DIM;
            int d0 = cc % D_DIM;
            #pragma unroll
            for (int mt = 0; mt < 2; mt++) {
                int r0 = rowBlk + wm * 32 + mt * 16 + lr;
                #pragma unroll
                for (int half = 0; half < 2; half++) {
                    int m = r0 + half * 8;
                    int b = m >> 11;
                    int s = m & (S_LEN - 1);
                    size_t off = ((size_t)(b * H_NUM + h) * S_LEN + s) * D_DIM + d0;
                    float v0 = acc[mt][nt][half * 2 + 0] + bb.x;
                    float v1 = acc[mt][nt][half * 2 + 1] + bb.y;
                    if (which == 0) {
                        *(float2*)(g_q + off) = make_float2(v0 * 0.125f, v1 * 0.125f);
                    } else if (which == 1) {
                        float h0 = rnd_tf32(v0), h1 = rnd_tf32(v1);
                        *(float2*)(g_khi + off) = make_float2(h0, h1);
                        *(float2*)(g_klo + off) =
                            make_float2(rnd_tf32(v0 - h0), rnd_tf32(v1 - h1));
                    } else {
                        *(float2*)(g_v + off) =
                            make_float2(rnd_tf32(v0), rnd_tf32(v1));
                    }
                }
            }
        } else {
            #pragma unroll
            for (int mt = 0; mt < 2; mt++) {
                int r0 = rowBlk + wm * 32 + mt * 16 + lr;
                #pragma unroll
                for (int half = 0; half < 2; half++) {
                    int m = r0 + half * 8;
                    float* p = Cout + (size_t)m * N + col;
                    *(float2*)p = make_float2(acc[mt][nt][half * 2 + 0] + bb.x,
                                              acc[mt][nt][half * 2 + 1] + bb.y);
                }
            }
        }
    }
}

// ---------------------------------------------------------------------------
// Tensor-core causal flash attention, 128-row Q tiles, 8 warps.
// Warp w owns Q rows [w*16, w*16+16). K/V tiles of 64 rows, pre-split/rounded.
// SMEM 48KB: khi[64x64], klo[64x64], v[64x64]. After QK, khi+klo hold P
// (128 x 64: warps 0-3 -> khi, warps 4-7 -> klo).
// Swizzles: K/Q/P side row*64 + (d ^ 4*(row&7)); V k*64 + (d ^ 8*(k&3)).
// Causal skip: warp computes only kt <= ktd = 2*qt + (w>>2).
// ---------------------------------------------------------------------------
__global__ void __launch_bounds__(256, 1) attn_mma_k()
{
    __shared__ float khi_sm[64 * 64];
    __shared__ float klo_sm[64 * 64];
    __shared__ float v_sm[64 * 64];

    const int tid  = threadIdx.x;
    const int lane = tid & 31;
    const int w    = tid >> 5;          // 0..7
    const int lr   = lane >> 2;
    const int lc   = lane & 3;
    const int qt   = blockIdx.x;        // 0..15 (128-row tiles)
    const int bh   = blockIdx.y;

    const float* qb  = g_q   + (size_t)bh * S_LEN * D_DIM;
    const float* khb = g_khi + (size_t)bh * S_LEN * D_DIM;
    const float* klb = g_klo + (size_t)bh * S_LEN * D_DIM;
    const float* vb  = g_v   + (size_t)bh * S_LEN * D_DIM;

    // Stage Q (pre-scaled fp32) in two 64-row halves through khi_sm; split hi/lo
    uint32_t qhi[8][4], qlo[8][4];
    for (int half = 0; half < 2; half++) {
        __syncthreads();
        for (int i = tid; i < 64 * 16; i += 256) {
            int row = i >> 4, d0 = (i & 15) * 4;
            float4 qv = *(const float4*)(qb + (size_t)(qt * 128 + half * 64 + row) * D_DIM + d0);
            *(float4*)&khi_sm[row * 64 + (d0 ^ (4 * (row & 7)))] = qv;
        }
        __syncthreads();
        if ((w >> 2) == half) {
            int rl = (w & 3) * 16;
            #pragma unroll
            for (int ks = 0; ks < 8; ks++) {
                const int kk = ks * 8;
                const int sw = 4 * lr;
                float x0 = khi_sm[(rl + lr) * 64     + ((kk + lc) ^ sw)];
                float x1 = khi_sm[(rl + lr + 8) * 64 + ((kk + lc) ^ sw)];
                float x2 = khi_sm[(rl + lr) * 64     + ((kk + lc + 4) ^ sw)];
                float x3 = khi_sm[(rl + lr + 8) * 64 + ((kk + lc + 4) ^ sw)];
                qhi[ks][0] = f2tf32(x0); qlo[ks][0] = f2tf32(x0 - __uint_as_float(qhi[ks][0]));
                qhi[ks][1] = f2tf32(x1); qlo[ks][1] = f2tf32(x1 - __uint_as_float(qhi[ks][1]));
                qhi[ks][2] = f2tf32(x2); qlo[ks][2] = f2tf32(x2 - __uint_as_float(qhi[ks][2]));
                qhi[ks][3] = f2tf32(x3); qlo[ks][3] = f2tf32(x3 - __uint_as_float(qhi[ks][3]));
            }
        }
    }

    float m_i[2] = {-1e30f, -1e30f};
    float l_i[2] = {0.f, 0.f};
    float oacc[8][4];
    #pragma unroll
    for (int nt = 0; nt < 8; nt++)
        #pragma unroll
        for (int i = 0; i < 4; i++) oacc[nt][i] = 0.f;

    // P buffer mapping for this warp
    float* pbuf = (w < 4) ? khi_sm : klo_sm;
    const int prl = (w & 3) * 16;                 // local P row base
    const int ktd = 2 * qt + (w >> 2);            // diagonal tile index
    const int ktmax = 2 * qt + 1;
    const int rowg0 = qt * 128 + w * 16 + lr;     // this thread's global rows
    const int rowg1 = rowg0 + 8;

    for (int kt = 0; kt <= ktmax; kt++) {
        __syncthreads();   // previous iteration fully consumed khi/klo/v
        // cp.async tile loads (pure copies; data pre-split/rounded)
        for (int i = tid; i < 64 * 16; i += 256) {
            int row = i >> 4, d0 = (i & 15) * 4;
            size_t base = (size_t)(kt * 64 + row) * D_DIM + d0;
            int offk = row * 64 + (d0 ^ (4 * (row & 7)));
            cp_async16(&khi_sm[offk], khb + base);
            cp_async16(&klo_sm[offk], klb + base);
            cp_async16(&v_sm[row * 64 + (d0 ^ (8 * (row & 3)))], vb + base);
        }
        cp_commit();
        cp_wait<0>();
        __syncthreads();

        const bool act = (kt <= ktd);
        float sacc[8][4];
        if (act) {
            #pragma unroll
            for (int nt = 0; nt < 8; nt++)
                #pragma unroll
                for (int i = 0; i < 4; i++) sacc[nt][i] = 0.f;

            #pragma unroll
            for (int ks = 0; ks < 8; ks++) {
                const int kk = ks * 8;
                #pragma unroll
                for (int nt = 0; nt < 8; nt++) {
                    int krow = nt * 8 + lr;
                    int sw   = 4 * lr;
                    int o0 = krow * 64 + ((kk + lc) ^ sw);
                    int o1 = krow * 64 + ((kk + lc + 4) ^ sw);
                    uint32_t bhi[2], blo[2];
                    bhi[0] = __float_as_uint(khi_sm[o0]);
                    bhi[1] = __float_as_uint(khi_sm[o1]);
                    blo[0] = __float_as_uint(klo_sm[o0]);
                    blo[1] = __float_as_uint(klo_sm[o1]);
                    mma_tf32(sacc[nt], qhi[ks], bhi);
                    mma_tf32(sacc[nt], qlo[ks], bhi);
                    mma_tf32(sacc[nt], qhi[ks], blo);
                }
            }

            if (kt == ktd) {   // diagonal tile: causal mask
                #pragma unroll
                for (int nt = 0; nt < 8; nt++) {
                    int colg = kt * 64 + nt * 8 + 2 * lc;
                    if (colg     > rowg0) sacc[nt][0] = -1e30f;
                    if (colg + 1 > rowg0) sacc[nt][1] = -1e30f;
                    if (colg     > rowg1) sacc[nt][2] = -1e30f;
                    if (colg + 1 > rowg1) sacc[nt][3] = -1e30f;
                }
            }

            // online softmax
            float mx0 = -1e30f, mx1 = -1e30f;
            #pragma unroll
            for (int nt = 0; nt < 8; nt++) {
                mx0 = fmaxf(mx0, fmaxf(sacc[nt][0], sacc[nt][1]));
                mx1 = fmaxf(mx1, fmaxf(sacc[nt][2], sacc[nt][3]));
            }
            mx0 = fmaxf(mx0, __shfl_xor_sync(0xffffffffu, mx0, 1));
            mx0 = fmaxf(mx0, __shfl_xor_sync(0xffffffffu, mx0, 2));
            mx1 = fmaxf(mx1, __shfl_xor_sync(0xffffffffu, mx1, 1));
            mx1 = fmaxf(mx1, __shfl_xor_sync(0xffffffffu, mx1, 2));
            float mn0 = fmaxf(m_i[0], mx0);
            float mn1 = fmaxf(m_i[1], mx1);
            float rs0 = __expf(m_i[0] - mn0);
            float rs1 = __expf(m_i[1] - mn1);

            float sum0 = 0.f, sum1 = 0.f;
            #pragma unroll
            for (int nt = 0; nt < 8; nt++) {
                sacc[nt][0] = __expf(sacc[nt][0] - mn0); sum0 += sacc[nt][0];
                sacc[nt][1] = __expf(sacc[nt][1] - mn0); sum0 += sacc[nt][1];
                sacc[nt][2] = __expf(sacc[nt][2] - mn1); sum1 += sacc[nt][2];
                sacc[nt][3] = __expf(sacc[nt][3] - mn1); sum1 += sacc[nt][3];
            }
            sum0 += __shfl_xor_sync(0xffffffffu, sum0, 1);
            sum0 += __shfl_xor_sync(0xffffffffu, sum0, 2);
            sum1 += __shfl_xor_sync(0xffffffffu, sum1, 1);
            sum1 += __shfl_xor_sync(0xffffffffu, sum1, 2);
            l_i[0] = l_i[0] * rs0 + sum0;
            l_i[1] = l_i[1] * rs1 + sum1;
            m_i[0] = mn0; m_i[1] = mn1;
            #pragma unroll
            for (int nt = 0; nt < 8; nt++) {
                oacc[nt][0] *= rs0; oacc[nt][1] *= rs0;
                oacc[nt][2] *= rs1; oacc[nt][3] *= rs1;
            }
        }

        __syncthreads();   // all warps done reading khi/klo before P overlay

        if (act) {
            // P (tf32-rounded) into pbuf, own rows only
            #pragma unroll
            for (int nt = 0; nt < 8; nt++) {
                int c0 = nt * 8 + 2 * lc;
                int sw = 4 * lr;           // (prl+lr[+8]) & 7 == lr
                *(float2*)&pbuf[(prl + lr) * 64     + (c0 ^ sw)] =
                    make_float2(rnd_tf32(sacc[nt][0]), rnd_tf32(sacc[nt][1]));
                *(float2*)&pbuf[(prl + lr + 8) * 64 + (c0 ^ sw)] =
                    make_float2(rnd_tf32(sacc[nt][2]), rnd_tf32(sacc[nt][3]));
            }
            __syncwarp();

            // O += P @ V
            #pragma unroll
            for (int ks = 0; ks < 8; ks++) {
                const int kk = ks * 8;
                const int sw = 4 * lr;
                uint32_t pa[4];
                pa[0] = __float_as_uint(pbuf[(prl + lr) * 64     + ((kk + lc) ^ sw)]);
                pa[1] = __float_as_uint(pbuf[(prl + lr + 8) * 64 + ((kk + lc) ^ sw)]);
                pa[2] = __float_as_uint(pbuf[(prl + lr) * 64     + ((kk + lc + 4) ^ sw)]);
                pa[3] = __float_as_uint(pbuf[(prl + lr + 8) * 64 + ((kk + lc + 4) ^ sw)]);
                #pragma unroll
                for (int nt = 0; nt < 8; nt++) {
                    int k0 = kk + lc;
                    int vsw = 8 * (k0 & 3);
                    uint32_t vb2[2];
                    vb2[0] = __float_as_uint(v_sm[k0 * 64       + ((nt * 8 + lr) ^ vsw)]);
                    vb2[1] = __float_as_uint(v_sm[(k0 + 4) * 64 + ((nt * 8 + lr) ^ vsw)]);
                    mma_tf32(oacc[nt], pa, vb2);
                }
            }
        }
    }

    // Epilogue: normalize, round, write TRANSPOSED to g_aoT [C][M]
    float inv0 = 1.f / l_i[0];
    float inv1 = 1.f / l_i[1];
    int b = bh >> 4, h = bh & 15;
    int mg0 = b * S_LEN + (qt * 128 + w * 16 + lr);   // global M index
    int mg1 = mg0 + 8;
    #pragma unroll
    for (int nt = 0; nt < 8; nt++) {
        int c = h * D_DIM + nt * 8 + 2 * lc;
        g_aoT[(size_t)c * M_DIM + mg0]       = rnd_tf32(oacc[nt][0] * inv0);
        g_aoT[(size_t)(c + 1) * M_DIM + mg0] = rnd_tf32(oacc[nt][1] * inv0);
        g_aoT[(size_t)c * M_DIM + mg1]       = rnd_tf32(oacc[nt][2] * inv1);
        g_aoT[(size_t)(c + 1) * M_DIM + mg1] = rnd_tf32(oacc[nt][3] * inv1);
    }
}

// ---------------------------------------------------------------------------
extern "C" void kernel_launch(void* const* d_in, const int* in_sizes, int n_in,
                              void* d_out, int out_size)
{
    const float* x      = (const float*)d_in[0];
    const float* w_qkv  = (const float*)d_in[1];
    const float* b_qkv  = (const float*)d_in[2];
    const float* w_proj = (const float*)d_in[3];
    const float* b_proj = (const float*)d_in[4];
    float* out = (float*)d_out;

    // 0) Prep: round+transpose x; round weights
    round_transpose_x_k<<<dim3(M_DIM / 32, C_DIM / 32), 256>>>(x);
    {
        int n4w = (C_DIM * 3 * C_DIM) / 4;
        round_w_k<1><<<(n4w + 255) / 256, 256>>>(w_qkv, n4w);
        int n4p = (C_DIM * C_DIM) / 4;
        round_w_k<2><<<(n4p + 255) / 256, 256>>>(w_proj, n4p);
    }

    // 1) QKV GEMM + bias -> g_q (scaled), g_khi/g_klo (split), g_v (rounded)
    sgemm_tf32_k<0><<<dim3((3 * C_DIM) / 128, M_DIM / 128), 256>>>(
        b_qkv, nullptr, 3 * C_DIM);

    // 2) Causal flash attention -> g_aoT (transposed, rounded)
    attn_mma_k<<<dim3(S_LEN / 128, BHN), 256>>>();

    // 3) Output projection + bias
    sgemm_tf32_k<1><<<dim3(C_DIM / 128, M_DIM / 128), 256>>>(
        b_proj, out, C_DIM);
}